// round 2
// baseline (speedup 1.0000x reference)
#include <cuda_runtime.h>
#include <stdint.h>

// ParallelTransport: out[e, c, :] = R(rho[e]) @ x[row[e], c, :]
// x: (1, N, 32, 2) fp32 ; edge_index: (2, E) int32 (JAX demotes int64->int32)
// rho: (E,) fp32 ; out: (1, E, 32, 2) fp32
//
// Each edge's x-row is 64 contiguous floats (256 B). 16 threads per edge,
// one float4 (2 channels) per thread. Memory-bound: ~410 MB out write,
// x gather served from L2 (x table = 12.8 MB, fits L2 entirely).

__global__ void __launch_bounds__(256)
pt_kernel(const float* __restrict__ x,
          const int* __restrict__ row,
          const float* __restrict__ rho,
          float4* __restrict__ out,
          long long total /* E * 16 */)
{
    long long tid = (long long)blockIdx.x * blockDim.x + threadIdx.x;
    if (tid >= total) return;

    long long e   = tid >> 4;
    int       sub = (int)(tid & 15);

    int   r  = __ldg(&row[e]);       // broadcast across the 16-lane group
    float rv = __ldg(&rho[e]);

    float s, c;
    __sincosf(rv, &s, &c);

    const float4* xp = reinterpret_cast<const float4*>(x + (long long)r * 64) + sub;
    float4 v = __ldg(xp);

    float4 o;
    o.x = fmaf(c, v.x, -s * v.y);   // c*x0 - s*x1
    o.y = fmaf(s, v.x,  c * v.y);   // s*x0 + c*x1
    o.z = fmaf(c, v.z, -s * v.w);
    o.w = fmaf(s, v.z,  c * v.w);

    out[tid] = o;
}

extern "C" void kernel_launch(void* const* d_in, const int* in_sizes, int n_in,
                              void* d_out, int out_size)
{
    const float* x    = (const float*)d_in[0];
    const int*   eidx = (const int*)d_in[1];   // (2, E): first E entries = row
    const float* rho  = (const float*)d_in[2];

    long long E = in_sizes[2];           // rho element count
    long long total = E * 16;            // 16 threads per edge

    int threads = 256;
    long long blocks = (total + threads - 1) / threads;

    pt_kernel<<<(unsigned)blocks, threads>>>(
        x, eidx /* row = edge_index[0] */, rho, (float4*)d_out, total);
}

// round 3
// speedup vs baseline: 1.7040x; 1.7040x over previous
#include <cuda_runtime.h>
#include <stdint.h>

// ParallelTransport: out[e, c, :] = R(rho[e]) @ x[row[e], c, :]
// x: (1, N, 32, 2) fp32 ; edge_index: (2, E) int32 ; rho: (E,) fp32
// out: (1, E, 32, 2) fp32
//
// 16 threads per edge, one float4 (2 channels) each. ITER=4 slots per thread
// processed in load-batched phases to get MLP~4 on the dependent gather
// (R2 profile showed latency-bound: DRAM 46%, issue 29%, nothing saturated).

#define ITER 4

__global__ void __launch_bounds__(256)
pt_kernel(const float* __restrict__ x,
          const int* __restrict__ row,
          const float* __restrict__ rho,
          float4* __restrict__ out,
          long long total /* E * 16 */)
{
    long long base = (long long)blockIdx.x * (256 * ITER) + threadIdx.x;

    long long slot[ITER];
    int   r[ITER];
    float rv[ITER];
    float4 v[ITER];

    // Phase 1: index + rho loads (L1-broadcast within 16-lane groups)
    #pragma unroll
    for (int i = 0; i < ITER; i++) {
        slot[i] = base + (long long)i * 256;
        long long e = slot[i] >> 4;
        bool ok = slot[i] < total;
        r[i]  = ok ? __ldg(&row[e]) : 0;
        rv[i] = ok ? __ldg(&rho[e]) : 0.0f;
    }

    // Phase 2: dependent gathers — 4 independent chains in flight
    #pragma unroll
    for (int i = 0; i < ITER; i++) {
        int sub = (int)(slot[i] & 15);
        const float4* xp =
            reinterpret_cast<const float4*>(x + (long long)r[i] * 64) + sub;
        v[i] = __ldg(xp);
    }

    // Phase 3: rotate + streaming store (don't thrash L2-resident x table)
    #pragma unroll
    for (int i = 0; i < ITER; i++) {
        if (slot[i] >= total) continue;
        float s, c;
        __sincosf(rv[i], &s, &c);
        float4 o;
        o.x = fmaf(c, v[i].x, -s * v[i].y);
        o.y = fmaf(s, v[i].x,  c * v[i].y);
        o.z = fmaf(c, v[i].z, -s * v[i].w);
        o.w = fmaf(s, v[i].z,  c * v[i].w);
        __stcs(&out[slot[i]], o);
    }
}

extern "C" void kernel_launch(void* const* d_in, const int* in_sizes, int n_in,
                              void* d_out, int out_size)
{
    const float* x    = (const float*)d_in[0];
    const int*   eidx = (const int*)d_in[1];   // (2, E): first E entries = row
    const float* rho  = (const float*)d_in[2];

    long long E = in_sizes[2];
    long long total = E * 16;                  // float4 slots

    int threads = 256;
    long long per_block = (long long)threads * ITER;
    long long blocks = (total + per_block - 1) / per_block;

    pt_kernel<<<(unsigned)blocks, threads>>>(
        x, eidx, rho, (float4*)d_out, total);
}